// round 16
// baseline (speedup 1.0000x reference)
#include <cuda_runtime.h>
#include <cuda_fp16.h>
#include <cstdint>

#define LNUM   4
#define BTOK   16384
#define DIN    2048
#define DOUT   2048
#define TILE_M 128
#define TILE_N 128
#define TILE_K 64
#define NKT    (DIN / TILE_K)                 // 32
#define MAX_TILES (BTOK / TILE_M + LNUM)      // 132
#define NSTAGES 3
#define HIST_BLOCKS 64
#define NPERSIST 304                          // 2 CTAs/SM x 152 SMs

// ---------------- scratch (device globals; zero-init, self-cleaning) --------
__device__ int      g_cnt32[LNUM], g_cnt64[LNUM], g_cursor[LNUM];
__device__ unsigned g_odd_or;
__device__ int      g_is64;
__device__ int      g_offsets[LNUM + 1];
__device__ int      g_perm[BTOK];
__device__ int      g_tile_expert[MAX_TILES];
__device__ int      g_tile_row[MAX_TILES];
__device__ int      g_ntiles;
__device__ int      g_tile_ctr;
__device__ __half   g_xh[(BTOK + TILE_M) * DIN];   // pre-permuted fp16 x (+pad)
__device__ __half   g_wh[LNUM * DIN * DOUT];       // fp16 W

// ---------------- side stream for the independent W-convert branch ----------
// Created once at static init. Streams/events are not device-memory
// allocations; the fork/join event pattern is the standard way to express a
// parallel branch inside stream capture.
static cudaStream_t g_s2;
static cudaEvent_t  g_ev_fork, g_ev_join;
namespace {
struct StreamInit {
    StreamInit() {
        cudaStreamCreateWithFlags(&g_s2, cudaStreamNonBlocking);
        cudaEventCreateWithFlags(&g_ev_fork, cudaEventDisableTiming);
        cudaEventCreateWithFlags(&g_ev_join, cudaEventDisableTiming);
    }
};
static StreamInit g_stream_init;
}

// ---------------- helpers ---------------------------------------------------
__device__ __forceinline__ uint32_t smem_u32(const void* p) {
    uint32_t a;
    asm("{ .reg .u64 t; cvta.to.shared.u64 t, %1; cvt.u32.u64 %0, t; }"
        : "=r"(a) : "l"(p));
    return a;
}
#define CP_ASYNC16(dst, src) \
    asm volatile("cp.async.cg.shared.global [%0], [%1], 16;" :: "r"(dst), "l"(src))
#define CP_COMMIT() asm volatile("cp.async.commit_group;" ::: "memory")
#define CP_WAIT(n)  asm volatile("cp.async.wait_group %0;" :: "n"(n) : "memory")

#define LDSM_X4(r0, r1, r2, r3, a) \
    asm volatile("ldmatrix.sync.aligned.m8n8.x4.shared.b16 {%0,%1,%2,%3}, [%4];" \
                 : "=r"(r0), "=r"(r1), "=r"(r2), "=r"(r3) : "r"(a))
#define LDSM_X4T(r0, r1, r2, r3, a) \
    asm volatile("ldmatrix.sync.aligned.m8n8.x4.trans.shared.b16 {%0,%1,%2,%3}, [%4];" \
                 : "=r"(r0), "=r"(r1), "=r"(r2), "=r"(r3) : "r"(a))
#define MMA16816(d, a, b0, b1)                                               \
    asm volatile("mma.sync.aligned.m16n8k16.row.col.f32.f16.f16.f32 "        \
        "{%0,%1,%2,%3}, {%4,%5,%6,%7}, {%8,%9}, {%0,%1,%2,%3};"              \
        : "+f"((d)[0]), "+f"((d)[1]), "+f"((d)[2]), "+f"((d)[3])             \
        : "r"((a)[0]), "r"((a)[1]), "r"((a)[2]), "r"((a)[3]), "r"(b0), "r"(b1))

// ---------------- hist: both dtype-interpretation counts + odd-word OR ------
__global__ void k_hist(const unsigned* __restrict__ w) {
    const int tid  = threadIdx.x;
    const int lane = tid & 31;
    const int j = blockIdx.x * 256 + tid;
    unsigned lo = w[2 * j], hi = w[2 * j + 1];   // int64 view
    unsigned v  = w[j];                          // int32 view
    if (hi) atomicOr(&g_odd_or, hi);
    int e64 = (int)(lo & 3u);
    unsigned m64 = __match_any_sync(0xffffffffu, e64);
    if (lane == (__ffs(m64) - 1)) atomicAdd(&g_cnt64[e64], __popc(m64));
    int e32 = (int)(v & 3u);
    unsigned m32 = __match_any_sync(0xffffffffu, e32);
    if (lane == (__ffs(m32) - 1)) atomicAdd(&g_cnt32[e32], __popc(m32));
}

// ---------------- W fp32 -> fp16 (independent branch, side stream) ----------
__global__ void k_convw(const float* __restrict__ W) {
    size_t i = ((size_t)blockIdx.x * 256 + threadIdx.x) * 8;
    float4 a = *(const float4*)(W + i);
    float4 c = *(const float4*)(W + i + 4);
    __half2 h[4];
    h[0] = __floats2half2_rn(a.x, a.y);
    h[1] = __floats2half2_rn(a.z, a.w);
    h[2] = __floats2half2_rn(c.x, c.y);
    h[3] = __floats2half2_rn(c.z, c.w);
    *(uint4*)(g_wh + i) = *(uint4*)h;
}

// ---------------- plan tiles; self-clean state for next replay --------------
__global__ void k_plan() {
    int is64 = (g_odd_or == 0u);
    g_is64 = is64;
    const int* cnt = is64 ? g_cnt64 : g_cnt32;
    g_offsets[0] = 0;
    for (int e = 0; e < LNUM; e++) g_offsets[e + 1] = g_offsets[e] + cnt[e];
    int nt = 0;
    for (int e = 0; e < LNUM; e++)
        for (int r = g_offsets[e]; r < g_offsets[e + 1]; r += TILE_M) {
            g_tile_expert[nt] = e; g_tile_row[nt] = r; nt++;
        }
    g_ntiles = nt;
    g_tile_ctr = 0;
    for (int e = 0; e < LNUM; e++) { g_cursor[e] = 0; g_cnt32[e] = 0; g_cnt64[e] = 0; }
    g_odd_or = 0u;
}

// ---------------- fused scatter + permuted fp16 convert ---------------------
__global__ void k_scatconv(const unsigned* __restrict__ w, const float* __restrict__ x) {
    __shared__ int s_p[8];
    const int tid = threadIdx.x;
    const int j0  = blockIdx.x * 8;

    if (tid < 8) {
        const int j = j0 + tid;
        int e = g_is64 ? (int)(w[2 * j] & 3u) : (int)(w[j] & 3u);
        unsigned mask = __match_any_sync(0x000000ffu, e);
        int leader = __ffs(mask) - 1;
        int rank   = __popc(mask & ((1u << tid) - 1u));
        int base   = 0;
        if (tid == leader) base = atomicAdd(&g_cursor[e], __popc(mask));
        base = __shfl_sync(0x000000ffu, base, leader);
        int p = g_offsets[e] + base + rank;
        s_p[tid] = p;
        g_perm[p] = j;
    }
    __syncthreads();

#pragma unroll
    for (int r = 0; r < 8; r++) {
        const int p = s_p[r];
        const float* src = x + (size_t)(j0 + r) * DIN + tid * 8;
        __half* dst = g_xh + (size_t)p * DIN + tid * 8;
        float4 a = *(const float4*)src;
        float4 c = *(const float4*)(src + 4);
        __half2 h[4];
        h[0] = __floats2half2_rn(a.x, a.y);
        h[1] = __floats2half2_rn(a.z, a.w);
        h[2] = __floats2half2_rn(c.x, c.y);
        h[3] = __floats2half2_rn(c.z, c.w);
        *(uint4*)dst = *(uint4*)h;
    }
}

// ---------------- GEMM: persistent CTAs; R15 (measured-best) ---------------
#define A_STG   16384
#define B_STG   16384
#define STG     (A_STG + B_STG)               // 32768
#define SMEM_TOTAL (NSTAGES * STG + 16)       // +16: tile-broadcast slot

__global__ void __launch_bounds__(256, 2)
gemm_kernel(const float* __restrict__ bias, float* __restrict__ out) {
    extern __shared__ char smem[];
    const uint32_t sb = smem_u32(smem);
    int* s_tile = (int*)(smem + NSTAGES * STG);

    const int tid    = threadIdx.x;
    const int lane   = tid & 31;
    const int wid    = tid >> 5;
    const int warp_m = wid & 3;               // 4 warps in M
    const int warp_n = wid >> 2;              // 2 warps in N
    const int ntiles = g_ntiles;
    const int total  = ntiles * (DOUT / TILE_N);

    // ---- tile-invariant address components ----
    uint32_t adst[4], bdst[4];
#pragma unroll
    for (int p = 0; p < 4; p++) {
        int s = tid + p * 256;                // A slot: r = s>>3, c = s&7
        int r = s >> 3, c = s & 7;
        adst[p] = (uint32_t)(r * 128 + ((c ^ (r & 7)) << 4));
        int kr = s >> 4, cb = s & 15;         // B slot
        bdst[p] = (uint32_t)(A_STG + kr * 256 +
                             ((((cb & 7) ^ (kr & 7)) | (cb & 8)) << 4));
    }
    const int l15 = lane & 15, lhi = lane >> 4, l7 = lane & 7;
    const uint32_t bRowOff = (uint32_t)(A_STG + l15 * 256);
    uint32_t bChunk[4];
#pragma unroll
    for (int f = 0; f < 4; f++)
        bChunk[f] = (uint32_t)(((((2 * f + lhi) ^ l7)) | (warp_n * 8)) << 4);
    uint32_t aChunk[4][2];
#pragma unroll
    for (int s = 0; s < 4; s++)
#pragma unroll
        for (int m = 0; m < 2; m++)
            aChunk[s][m] = (uint32_t)((warp_m * 32 + m * 16 + l15) * 128 +
                                      (((2 * s + lhi) ^ l7) << 4));

    // ---- cp.async source pointers (rebased per tile) ----
    const __half* asrc[4];
    const __half* bsrc[4];
    auto set_srcs = [&](int row0_, int e_, int n0_) {
        const __half* xbase = g_xh + (size_t)row0_ * DIN;
        const __half* wbase = g_wh + (size_t)e_ * DIN * DOUT + n0_;
#pragma unroll
        for (int p = 0; p < 4; p++) {
            int s = tid + p * 256;
            asrc[p] = xbase + (size_t)(s >> 3) * DIN + (s & 7) * 8;
            bsrc[p] = wbase + (size_t)(s >> 4) * DOUT + (s & 15) * 8;
        }
    };
    auto issue_stage = [&](int buf) {
        uint32_t base = sb + buf * STG;
#pragma unroll
        for (int p = 0; p < 4; p++) CP_ASYNC16(base + adst[p], asrc[p]);
#pragma unroll
        for (int p = 0; p < 4; p++) CP_ASYNC16(base + bdst[p], bsrc[p]);
#pragma unroll
        for (int p = 0; p < 4; p++) { asrc[p] += TILE_K; bsrc[p] += (size_t)TILE_K * DOUT; }
    };

    // ---- fetch + decode first tile; prime pipeline ----
    if (tid == 0) *s_tile = atomicAdd(&g_tile_ctr, 1);
    __syncthreads();
    int lin = *s_tile;
    if (lin >= total) return;
    int t    = lin % ntiles;                  // tile-fast (proven order)
    int n0   = (lin / ntiles) * TILE_N;
    int e    = g_tile_expert[t];
    int row0 = g_tile_row[t];

    set_srcs(row0, e, n0);
    issue_stage(0); CP_COMMIT();
    issue_stage(1); CP_COMMIT();

    for (;;) {
        float acc[2][8][4];
#pragma unroll
        for (int m = 0; m < 2; m++)
#pragma unroll
            for (int n = 0; n < 8; n++)
#pragma unroll
                for (int q = 0; q < 4; q++) acc[m][n][q] = 0.0f;

        // ================= R13/R15 mainloop (unchanged) =================
#pragma unroll 3
        for (int i = 0; i < NKT; i++) {
            const int buf = i % NSTAGES;
            CP_WAIT(1);
            __syncthreads();
            const uint32_t base = sb + buf * STG;

#pragma unroll
            for (int s = 0; s < 4; s++) {
                uint32_t a[2][4];
#pragma unroll
                for (int m = 0; m < 2; m++)
                    LDSM_X4(a[m][0], a[m][1], a[m][2], a[m][3], base + aChunk[s][m]);
                const uint32_t brow = base + bRowOff + s * 4096;

                uint32_t b[2][4];
                LDSM_X4T(b[0][0], b[0][1], b[0][2], b[0][3], brow + bChunk[0]);
#pragma unroll
                for (int f = 0; f < 4; f++) {
                    const int cur = f & 1;
                    if (f < 3)
                        LDSM_X4T(b[cur ^ 1][0], b[cur ^ 1][1],
                                 b[cur ^ 1][2], b[cur ^ 1][3], brow + bChunk[f + 1]);
                    MMA16816(acc[0][2 * f],     a[0], b[cur][0], b[cur][1]);
                    MMA16816(acc[1][2 * f],     a[1], b[cur][0], b[cur][1]);
                    MMA16816(acc[0][2 * f + 1], a[0], b[cur][2], b[cur][3]);
                    MMA16816(acc[1][2 * f + 1], a[1], b[cur][2], b[cur][3]);
                }
                if (s == 0) {
                    if (i + 2 < NKT) issue_stage((i + 2) % NSTAGES);
                    CP_COMMIT();
                }
            }
        }
        // ================================================================

        // ---- boundary: fetch next tile, pre-issue its k0/k1 ----
        if (tid == 0) *s_tile = atomicAdd(&g_tile_ctr, 1);
        __syncthreads();                      // buf1 free + s_tile published
        const int nlin = *s_tile;
        const bool hn = nlin < total;
        int ne = 0, nrow0 = 0, nn0 = 0;
        if (hn) {
            int nt_ = nlin % ntiles;
            nn0   = (nlin / ntiles) * TILE_N;
            ne    = g_tile_expert[nt_];
            nrow0 = g_tile_row[nt_];
            set_srcs(nrow0, ne, nn0);
            issue_stage(0); CP_COMMIT();      // buf0 free since i=31's barrier
            issue_stage(1); CP_COMMIT();
        }

        // ---- epilogue (next tile's loads in flight) ----
        const int endRow = g_offsets[e + 1];
        const int r0 = warp_m * 32 + (lane >> 2);
        int  tok[4];
        bool ok[4];
#pragma unroll
        for (int q = 0; q < 4; q++) {
            int r = row0 + r0 + q * 8;
            ok[q]  = r < endRow;
            tok[q] = ok[q] ? g_perm[r] : 0;
        }
        const float* bcol = bias + (size_t)e * DOUT + n0 + warp_n * 64 + (lane & 3) * 2;
#pragma unroll
        for (int m = 0; m < 2; m++)
#pragma unroll
            for (int n = 0; n < 8; n++) {
                float2 bb = *(const float2*)(bcol + n * 8);
                int col = n0 + warp_n * 64 + n * 8 + (lane & 3) * 2;
                if (ok[m * 2])
                    *(float2*)(out + (size_t)tok[m * 2] * DOUT + col) =
                        make_float2(acc[m][n][0] + bb.x, acc[m][n][1] + bb.y);
                if (ok[m * 2 + 1])
                    *(float2*)(out + (size_t)tok[m * 2 + 1] * DOUT + col) =
                        make_float2(acc[m][n][2] + bb.x, acc[m][n][3] + bb.y);
            }

        if (!hn) break;
        e = ne; row0 = nrow0; n0 = nn0;
    }
}

// ---------------- launch ----------------------------------------------------
#define W_BLOCKS ((LNUM * DIN * DOUT) / 2048)    // 8192
extern "C" void kernel_launch(void* const* d_in, const int* in_sizes, int n_in,
                              void* d_out, int out_size) {
    const float* x   = (const float*)d_in[0];
    const void*  idx = d_in[1];
    const float* W   = (const float*)d_in[2];
    const float* b   = (const float*)d_in[3];
    float* out = (float*)d_out;

    cudaFuncSetAttribute(gemm_kernel,
                         cudaFuncAttributeMaxDynamicSharedMemorySize, SMEM_TOTAL);

    // fork: W-convert (independent) on side stream, overlapping the
    // hist -> plan -> scatter+convert chain on the main stream.
    cudaEventRecord(g_ev_fork, 0);
    cudaStreamWaitEvent(g_s2, g_ev_fork, 0);
    k_convw<<<W_BLOCKS, 256, 0, g_s2>>>(W);

    k_hist<<<HIST_BLOCKS, 256>>>((const unsigned*)idx);
    k_plan<<<1, 1>>>();
    k_scatconv<<<BTOK / 8, 256>>>((const unsigned*)idx, x);

    // join: GEMM needs both branches
    cudaEventRecord(g_ev_join, g_s2);
    cudaStreamWaitEvent(0, g_ev_join, 0);
    gemm_kernel<<<NPERSIST, 256, SMEM_TOTAL>>>(b, out);
}

// round 17
// speedup vs baseline: 1.0113x; 1.0113x over previous
#include <cuda_runtime.h>
#include <cuda_fp16.h>
#include <cstdint>

#define LNUM   4
#define BTOK   16384
#define DIN    2048
#define DOUT   2048
#define TILE_M 128
#define TILE_N 128
#define TILE_K 64
#define NKT    (DIN / TILE_K)                 // 32
#define MAX_TILES (BTOK / TILE_M + LNUM)      // 132
#define NSTAGES 3
#define HIST_BLOCKS 64
#define NPERSIST 304                          // 2 CTAs/SM x 152 SMs

// ---------------- scratch (device globals; zero-init, self-cleaning) --------
__device__ int      g_cnt32[LNUM], g_cnt64[LNUM], g_cursor[LNUM];
__device__ unsigned g_odd_or;
__device__ int      g_done;
__device__ int      g_is64;
__device__ int      g_offsets[LNUM + 1];
__device__ int      g_perm[BTOK];
__device__ int      g_tile_expert[MAX_TILES];
__device__ int      g_tile_row[MAX_TILES];
__device__ int      g_ntiles;
__device__ int      g_tile_ctr;
__device__ __half   g_xh[(BTOK + TILE_M) * DIN];   // pre-permuted fp16 x (+pad)
__device__ __half   g_wh[LNUM * DIN * DOUT];       // fp16 W

// ---------------- helpers ---------------------------------------------------
__device__ __forceinline__ uint32_t smem_u32(const void* p) {
    uint32_t a;
    asm("{ .reg .u64 t; cvta.to.shared.u64 t, %1; cvt.u32.u64 %0, t; }"
        : "=r"(a) : "l"(p));
    return a;
}
#define CP_ASYNC16(dst, src) \
    asm volatile("cp.async.cg.shared.global [%0], [%1], 16;" :: "r"(dst), "l"(src))
#define CP_COMMIT() asm volatile("cp.async.commit_group;" ::: "memory")
#define CP_WAIT(n)  asm volatile("cp.async.wait_group %0;" :: "n"(n) : "memory")

#define LDSM_X4(r0, r1, r2, r3, a) \
    asm volatile("ldmatrix.sync.aligned.m8n8.x4.shared.b16 {%0,%1,%2,%3}, [%4];" \
                 : "=r"(r0), "=r"(r1), "=r"(r2), "=r"(r3) : "r"(a))
#define LDSM_X4T(r0, r1, r2, r3, a) \
    asm volatile("ldmatrix.sync.aligned.m8n8.x4.trans.shared.b16 {%0,%1,%2,%3}, [%4];" \
                 : "=r"(r0), "=r"(r1), "=r"(r2), "=r"(r3) : "r"(a))
#define MMA16816(d, a, b0, b1)                                               \
    asm volatile("mma.sync.aligned.m16n8k16.row.col.f32.f16.f16.f32 "        \
        "{%0,%1,%2,%3}, {%4,%5,%6,%7}, {%8,%9}, {%0,%1,%2,%3};"              \
        : "+f"((d)[0]), "+f"((d)[1]), "+f"((d)[2]), "+f"((d)[3])             \
        : "r"((a)[0]), "r"((a)[1]), "r"((a)[2]), "r"((a)[3]), "r"(b0), "r"(b1))

// ---------------- launch 1: hist + inline plan (last block) + W convert -----
// Counters zeroed by the previous replay's plan (zero-init on run 1).
__global__ void k_prep(const unsigned* __restrict__ w, const float* __restrict__ W) {
    const int b   = blockIdx.x;
    const int tid = threadIdx.x;
    if (b < HIST_BLOCKS) {
        __shared__ int s_last;
        const int lane = tid & 31;
        const int j = b * 256 + tid;
        unsigned lo = w[2 * j], hi = w[2 * j + 1];   // int64 view
        unsigned v  = w[j];                          // int32 view
        if (hi) atomicOr(&g_odd_or, hi);
        int e64 = (int)(lo & 3u);
        unsigned m64 = __match_any_sync(0xffffffffu, e64);
        if (lane == (__ffs(m64) - 1)) atomicAdd(&g_cnt64[e64], __popc(m64));
        int e32 = (int)(v & 3u);
        unsigned m32 = __match_any_sync(0xffffffffu, e32);
        if (lane == (__ffs(m32) - 1)) atomicAdd(&g_cnt32[e32], __popc(m32));

        // last hist block runs the (serial) plan inline
        __threadfence();
        __syncthreads();
        if (tid == 0)
            s_last = (atomicAdd(&g_done, 1) == HIST_BLOCKS - 1) ? 1 : 0;
        __syncthreads();
        if (s_last && tid == 0) {
            int is64 = (g_odd_or == 0u);
            g_is64 = is64;
            const int* cnt = is64 ? g_cnt64 : g_cnt32;
            g_offsets[0] = 0;
            for (int e = 0; e < LNUM; e++) g_offsets[e + 1] = g_offsets[e] + cnt[e];
            int nt = 0;
            for (int e = 0; e < LNUM; e++)
                for (int r = g_offsets[e]; r < g_offsets[e + 1]; r += TILE_M) {
                    g_tile_expert[nt] = e; g_tile_row[nt] = r; nt++;
                }
            g_ntiles = nt;
            g_tile_ctr = 0;
            for (int e = 0; e < LNUM; e++) {
                g_cursor[e] = 0; g_cnt32[e] = 0; g_cnt64[e] = 0;
            }
            g_odd_or = 0u;
            g_done = 0;
            __threadfence();
        }
    } else {
        size_t i = ((size_t)(b - HIST_BLOCKS) * 256 + tid) * 8;
        float4 a = *(const float4*)(W + i);
        float4 c = *(const float4*)(W + i + 4);
        __half2 h[4];
        h[0] = __floats2half2_rn(a.x, a.y);
        h[1] = __floats2half2_rn(a.z, a.w);
        h[2] = __floats2half2_rn(c.x, c.y);
        h[3] = __floats2half2_rn(c.z, c.w);
        *(uint4*)(g_wh + i) = *(uint4*)h;
    }
}

// ---------------- launch 2: fused scatter + permuted fp16 convert -----------
__global__ void k_scatconv(const unsigned* __restrict__ w, const float* __restrict__ x) {
    __shared__ int s_p[8];
    const int tid = threadIdx.x;
    const int j0  = blockIdx.x * 8;

    if (tid < 8) {
        const int j = j0 + tid;
        int e = g_is64 ? (int)(w[2 * j] & 3u) : (int)(w[j] & 3u);
        unsigned mask = __match_any_sync(0x000000ffu, e);
        int leader = __ffs(mask) - 1;
        int rank   = __popc(mask & ((1u << tid) - 1u));
        int base   = 0;
        if (tid == leader) base = atomicAdd(&g_cursor[e], __popc(mask));
        base = __shfl_sync(0x000000ffu, base, leader);
        int p = g_offsets[e] + base + rank;
        s_p[tid] = p;
        g_perm[p] = j;
    }
    __syncthreads();

#pragma unroll
    for (int r = 0; r < 8; r++) {
        const int p = s_p[r];
        const float* src = x + (size_t)(j0 + r) * DIN + tid * 8;
        __half* dst = g_xh + (size_t)p * DIN + tid * 8;
        float4 a = *(const float4*)src;
        float4 c = *(const float4*)(src + 4);
        __half2 h[4];
        h[0] = __floats2half2_rn(a.x, a.y);
        h[1] = __floats2half2_rn(a.z, a.w);
        h[2] = __floats2half2_rn(c.x, c.y);
        h[3] = __floats2half2_rn(c.z, c.w);
        *(uint4*)dst = *(uint4*)h;
    }
}

// ---------------- GEMM: persistent CTAs; R15 (measured-best, unchanged) -----
#define A_STG   16384
#define B_STG   16384
#define STG     (A_STG + B_STG)               // 32768
#define SMEM_TOTAL (NSTAGES * STG + 16)       // +16: tile-broadcast slot

__global__ void __launch_bounds__(256, 2)
gemm_kernel(const float* __restrict__ bias, float* __restrict__ out) {
    extern __shared__ char smem[];
    const uint32_t sb = smem_u32(smem);
    int* s_tile = (int*)(smem + NSTAGES * STG);

    const int tid    = threadIdx.x;
    const int lane   = tid & 31;
    const int wid    = tid >> 5;
    const int warp_m = wid & 3;               // 4 warps in M
    const int warp_n = wid >> 2;              // 2 warps in N
    const int ntiles = g_ntiles;
    const int total  = ntiles * (DOUT / TILE_N);

    // ---- tile-invariant address components ----
    uint32_t adst[4], bdst[4];
#pragma unroll
    for (int p = 0; p < 4; p++) {
        int s = tid + p * 256;                // A slot: r = s>>3, c = s&7
        int r = s >> 3, c = s & 7;
        adst[p] = (uint32_t)(r * 128 + ((c ^ (r & 7)) << 4));
        int kr = s >> 4, cb = s & 15;         // B slot
        bdst[p] = (uint32_t)(A_STG + kr * 256 +
                             ((((cb & 7) ^ (kr & 7)) | (cb & 8)) << 4));
    }
    const int l15 = lane & 15, lhi = lane >> 4, l7 = lane & 7;
    const uint32_t bRowOff = (uint32_t)(A_STG + l15 * 256);
    uint32_t bChunk[4];
#pragma unroll
    for (int f = 0; f < 4; f++)
        bChunk[f] = (uint32_t)(((((2 * f + lhi) ^ l7)) | (warp_n * 8)) << 4);
    uint32_t aChunk[4][2];
#pragma unroll
    for (int s = 0; s < 4; s++)
#pragma unroll
        for (int m = 0; m < 2; m++)
            aChunk[s][m] = (uint32_t)((warp_m * 32 + m * 16 + l15) * 128 +
                                      (((2 * s + lhi) ^ l7) << 4));

    // ---- cp.async source pointers (rebased per tile) ----
    const __half* asrc[4];
    const __half* bsrc[4];
    auto set_srcs = [&](int row0_, int e_, int n0_) {
        const __half* xbase = g_xh + (size_t)row0_ * DIN;
        const __half* wbase = g_wh + (size_t)e_ * DIN * DOUT + n0_;
#pragma unroll
        for (int p = 0; p < 4; p++) {
            int s = tid + p * 256;
            asrc[p] = xbase + (size_t)(s >> 3) * DIN + (s & 7) * 8;
            bsrc[p] = wbase + (size_t)(s >> 4) * DOUT + (s & 15) * 8;
        }
    };
    auto issue_stage = [&](int buf) {
        uint32_t base = sb + buf * STG;
#pragma unroll
        for (int p = 0; p < 4; p++) CP_ASYNC16(base + adst[p], asrc[p]);
#pragma unroll
        for (int p = 0; p < 4; p++) CP_ASYNC16(base + bdst[p], bsrc[p]);
#pragma unroll
        for (int p = 0; p < 4; p++) { asrc[p] += TILE_K; bsrc[p] += (size_t)TILE_K * DOUT; }
    };

    // ---- fetch + decode first tile; prime pipeline ----
    if (tid == 0) *s_tile = atomicAdd(&g_tile_ctr, 1);
    __syncthreads();
    int lin = *s_tile;
    if (lin >= total) return;
    int t    = lin % ntiles;                  // tile-fast (proven order)
    int n0   = (lin / ntiles) * TILE_N;
    int e    = g_tile_expert[t];
    int row0 = g_tile_row[t];

    set_srcs(row0, e, n0);
    issue_stage(0); CP_COMMIT();
    issue_stage(1); CP_COMMIT();

    for (;;) {
        float acc[2][8][4];
#pragma unroll
        for (int m = 0; m < 2; m++)
#pragma unroll
            for (int n = 0; n < 8; n++)
#pragma unroll
                for (int q = 0; q < 4; q++) acc[m][n][q] = 0.0f;

        // ================= R13/R15 mainloop (unchanged) =================
#pragma unroll 3
        for (int i = 0; i < NKT; i++) {
            const int buf = i % NSTAGES;
            CP_WAIT(1);
            __syncthreads();
            const uint32_t base = sb + buf * STG;

#pragma unroll
            for (int s = 0; s < 4; s++) {
                uint32_t a[2][4];
#pragma unroll
                for (int m = 0; m < 2; m++)
                    LDSM_X4(a[m][0], a[m][1], a[m][2], a[m][3], base + aChunk[s][m]);
                const uint32_t brow = base + bRowOff + s * 4096;

                uint32_t b[2][4];
                LDSM_X4T(b[0][0], b[0][1], b[0][2], b[0][3], brow + bChunk[0]);
#pragma unroll
                for (int f = 0; f < 4; f++) {
                    const int cur = f & 1;
                    if (f < 3)
                        LDSM_X4T(b[cur ^ 1][0], b[cur ^ 1][1],
                                 b[cur ^ 1][2], b[cur ^ 1][3], brow + bChunk[f + 1]);
                    MMA16816(acc[0][2 * f],     a[0], b[cur][0], b[cur][1]);
                    MMA16816(acc[1][2 * f],     a[1], b[cur][0], b[cur][1]);
                    MMA16816(acc[0][2 * f + 1], a[0], b[cur][2], b[cur][3]);
                    MMA16816(acc[1][2 * f + 1], a[1], b[cur][2], b[cur][3]);
                }
                if (s == 0) {
                    if (i + 2 < NKT) issue_stage((i + 2) % NSTAGES);
                    CP_COMMIT();
                }
            }
        }
        // ================================================================

        // ---- boundary: fetch next tile, pre-issue its k0/k1 ----
        if (tid == 0) *s_tile = atomicAdd(&g_tile_ctr, 1);
        __syncthreads();                      // buf1 free + s_tile published
        const int nlin = *s_tile;
        const bool hn = nlin < total;
        int ne = 0, nrow0 = 0, nn0 = 0;
        if (hn) {
            int nt_ = nlin % ntiles;
            nn0   = (nlin / ntiles) * TILE_N;
            ne    = g_tile_expert[nt_];
            nrow0 = g_tile_row[nt_];
            set_srcs(nrow0, ne, nn0);
            issue_stage(0); CP_COMMIT();      // buf0 free since i=31's barrier
            issue_stage(1); CP_COMMIT();
        }

        // ---- epilogue (next tile's loads in flight) ----
        const int endRow = g_offsets[e + 1];
        const int r0 = warp_m * 32 + (lane >> 2);
        int  tok[4];
        bool ok[4];
#pragma unroll
        for (int q = 0; q < 4; q++) {
            int r = row0 + r0 + q * 8;
            ok[q]  = r < endRow;
            tok[q] = ok[q] ? g_perm[r] : 0;
        }
        const float* bcol = bias + (size_t)e * DOUT + n0 + warp_n * 64 + (lane & 3) * 2;
#pragma unroll
        for (int m = 0; m < 2; m++)
#pragma unroll
            for (int n = 0; n < 8; n++) {
                float2 bb = *(const float2*)(bcol + n * 8);
                int col = n0 + warp_n * 64 + n * 8 + (lane & 3) * 2;
                if (ok[m * 2])
                    *(float2*)(out + (size_t)tok[m * 2] * DOUT + col) =
                        make_float2(acc[m][n][0] + bb.x, acc[m][n][1] + bb.y);
                if (ok[m * 2 + 1])
                    *(float2*)(out + (size_t)tok[m * 2 + 1] * DOUT + col) =
                        make_float2(acc[m][n][2] + bb.x, acc[m][n][3] + bb.y);
            }

        if (!hn) break;
        e = ne; row0 = nrow0; n0 = nn0;
    }
}

// ---------------- launch ----------------------------------------------------
#define W_BLOCKS ((LNUM * DIN * DOUT) / 2048)    // 8192
extern "C" void kernel_launch(void* const* d_in, const int* in_sizes, int n_in,
                              void* d_out, int out_size) {
    const float* x   = (const float*)d_in[0];
    const void*  idx = d_in[1];
    const float* W   = (const float*)d_in[2];
    const float* b   = (const float*)d_in[3];
    float* out = (float*)d_out;

    cudaFuncSetAttribute(gemm_kernel,
                         cudaFuncAttributeMaxDynamicSharedMemorySize, SMEM_TOTAL);

    k_prep<<<HIST_BLOCKS + W_BLOCKS, 256>>>((const unsigned*)idx, W);
    k_scatconv<<<BTOK / 8, 256>>>((const unsigned*)idx, x);
    gemm_kernel<<<NPERSIST, 256, SMEM_TOTAL>>>(b, out);
}